// round 1
// baseline (speedup 1.0000x reference)
#include <cuda_runtime.h>
#include <cuda_bf16.h>
#include <mma.h>
#include <cstdint>

using namespace nvcuda;

#define NNODE 100000
#define NEDGE 200000
#define NGRAPH 5000
#define NLAYER 5
// padded dims
#define KA 304      // agg / h2 stride (EMB=300 padded to mult of 16)
#define NT 608      // T stride (600 padded)
#define NB1 640     // W1 padded cols
#define NB2 320     // W2 padded cols

// ---------------- device scratch (no allocations allowed) ----------------
__device__ float g_h2[(size_t)NNODE * KA];     // pre-norm layer output (and initial emb)
__device__ float g_agg[(size_t)NNODE * KA];    // aggregated messages
__device__ float g_T[(size_t)NNODE * NT];      // hidden (after first linear + relu)
__device__ float g_W1p[NLAYER * KA * NB1];
__device__ float g_b1p[NLAYER * NB1];
__device__ float g_W2p[NLAYER * NT * NB2];
__device__ float g_b2p[NLAYER * NB2];
__device__ float g_e1p[NLAYER * 6 * KA];
__device__ float g_e2p[NLAYER * 3 * KA];
__device__ float g_scale[KA];
__device__ float g_shift[KA];
__device__ float g_stats[2 * KA];
__device__ int   g_deg[NNODE];
__device__ int   g_cursor[NNODE];
__device__ int   g_rowptr[NNODE + 1];
__device__ int   g_srclist[NEDGE];
__device__ int   g_ecnt[(size_t)NNODE * 9];    // per-node: 6 bond-type counts + 3 dir counts
__device__ int   g_gstart[NGRAPH + 1];
__device__ float g_ginv[NGRAPH];

// ---------------- setup kernels ----------------
__global__ void k_zero() {
    int idx = blockIdx.x * blockDim.x + threadIdx.x;
    if (idx < NNODE) { g_deg[idx] = 0; g_cursor[idx] = 0; }
    if (idx < NNODE * 9) g_ecnt[idx] = 0;
}

__global__ void k_prep_w1(const float* __restrict__ W1, const float* __restrict__ b1) {
    int idx = blockIdx.x * blockDim.x + threadIdx.x;
    if (idx < NLAYER * KA * NB1) {
        int n = idx % NB1;
        int k = (idx / NB1) % KA;
        int l = idx / (NB1 * KA);
        g_W1p[idx] = (k < 300 && n < 600) ? W1[((size_t)l * 300 + k) * 600 + n] : 0.f;
    }
    if (idx < NLAYER * NB1) {
        int n = idx % NB1, l = idx / NB1;
        g_b1p[idx] = (n < 600) ? b1[l * 600 + n] : 0.f;
    }
}

__global__ void k_prep_w2(const float* __restrict__ W2, const float* __restrict__ b2) {
    int idx = blockIdx.x * blockDim.x + threadIdx.x;
    if (idx < NLAYER * NT * NB2) {
        int n = idx % NB2;
        int k = (idx / NB2) % NT;
        int l = idx / (NB2 * NT);
        g_W2p[idx] = (k < 600 && n < 300) ? W2[((size_t)l * 600 + k) * 300 + n] : 0.f;
    }
    if (idx < NLAYER * NB2) {
        int n = idx % NB2, l = idx / NB2;
        g_b2p[idx] = (n < 300) ? b2[l * 300 + n] : 0.f;
    }
}

__global__ void k_prep_small(const float* __restrict__ e1, const float* __restrict__ e2) {
    int idx = blockIdx.x * blockDim.x + threadIdx.x;
    if (idx < NLAYER * 6 * KA) {
        int c = idx % KA, r = idx / KA;   // r = l*6 + t
        g_e1p[idx] = (c < 300) ? e1[(size_t)r * 300 + c] : 0.f;
    }
    if (idx < NLAYER * 3 * KA) {
        int c = idx % KA, r = idx / KA;   // r = l*3 + d
        g_e2p[idx] = (c < 300) ? e2[(size_t)r * 300 + c] : 0.f;
    }
    if (idx < KA) { g_scale[idx] = 1.f; g_shift[idx] = 0.f; }  // identity affine for layer 0
}

__global__ void k_count(const int* __restrict__ edge_index, const int* __restrict__ edge_attr) {
    int e = blockIdx.x * blockDim.x + threadIdx.x;
    if (e >= NEDGE) return;
    int dst = edge_index[NEDGE + e];
    int a0 = edge_attr[2 * e];
    int a1 = edge_attr[2 * e + 1];
    atomicAdd(&g_deg[dst], 1);
    atomicAdd(&g_ecnt[(size_t)dst * 9 + a0], 1);
    atomicAdd(&g_ecnt[(size_t)dst * 9 + 6 + a1], 1);
}

// single-block exclusive scan of g_deg -> g_rowptr
__global__ void k_scan() {
    __shared__ int wsum[32];
    __shared__ int carry;
    int t = threadIdx.x;       // 1024 threads
    int lane = t & 31, w = t >> 5;
    if (t == 0) carry = 0;
    __syncthreads();
    for (int base = 0; base < NNODE; base += 1024) {
        int v = (base + t < NNODE) ? g_deg[base + t] : 0;
        int s = v;
        #pragma unroll
        for (int o = 1; o < 32; o <<= 1) {
            int u = __shfl_up_sync(0xffffffffu, s, o);
            if (lane >= o) s += u;
        }
        if (lane == 31) wsum[w] = s;
        __syncthreads();
        if (w == 0) {
            int ws = wsum[lane];
            #pragma unroll
            for (int o = 1; o < 32; o <<= 1) {
                int u = __shfl_up_sync(0xffffffffu, ws, o);
                if (lane >= o) ws += u;
            }
            wsum[lane] = ws;
        }
        __syncthreads();
        int excl = s - v + (w > 0 ? wsum[w - 1] : 0) + carry;
        if (base + t < NNODE) g_rowptr[base + t] = excl;
        int total = wsum[31];
        __syncthreads();
        if (t == 0) carry += total;
        __syncthreads();
    }
    if (t == 0) g_rowptr[NNODE] = carry;
}

__global__ void k_fill(const int* __restrict__ edge_index) {
    int e = blockIdx.x * blockDim.x + threadIdx.x;
    if (e >= NEDGE) return;
    int dst = edge_index[NEDGE + e];
    int src = edge_index[e];
    int pos = g_rowptr[dst] + atomicAdd(&g_cursor[dst], 1);
    g_srclist[pos] = src;
}

__global__ void k_h0(const int* __restrict__ x,
                     const float* __restrict__ emb1, const float* __restrict__ emb2) {
    size_t idx = (size_t)blockIdx.x * blockDim.x + threadIdx.x;
    if (idx >= (size_t)NNODE * KA) return;
    int c = (int)(idx % KA);
    int i = (int)(idx / KA);
    if (c < 300) {
        int a0 = x[2 * i], a1 = x[2 * i + 1];
        g_h2[idx] = emb1[(size_t)a0 * 300 + c] + emb2[(size_t)a1 * 300 + c];
    } else {
        g_h2[idx] = 0.f;
    }
}

__global__ void k_gstart(const int* __restrict__ batch) {
    int i = blockIdx.x * blockDim.x + threadIdx.x;
    if (i >= NNODE) return;
    int b = batch[i];
    int bp = (i == 0) ? -1 : batch[i - 1];
    for (int g = bp + 1; g <= b; g++) g_gstart[g] = i;
    if (i == NNODE - 1) {
        for (int g = b + 1; g <= NGRAPH; g++) g_gstart[g] = NNODE;
    }
}

__global__ void k_ginv() {
    int g = blockIdx.x * blockDim.x + threadIdx.x;
    if (g >= NGRAPH) return;
    int c = g_gstart[g + 1] - g_gstart[g];
    g_ginv[g] = (c > 0) ? (1.f / (float)c) : 0.f;
}

// ---------------- per-layer kernels ----------------

// agg[i] = aff(h2[i]) + (e1[0]+e2[0]) + sum_t cnt6[t]*e1[t] + sum_d cnt3[d]*e2[d]
//          + sum_{j in in(i)} aff(h2[j])
// where aff = batchnorm affine (+optional relu) of PREVIOUS layer output.
__global__ void k_agg(int l, int relu) {
    int i = blockIdx.x;
    int t = threadIdx.x;     // 96 threads, 76 active (304/4 float4 chunks)
    __shared__ int scnt[9];
    __shared__ int srange[2];
    if (t < 9) scnt[t] = g_ecnt[(size_t)i * 9 + t];
    else if (t == 9) srange[0] = g_rowptr[i];
    else if (t == 10) srange[1] = g_rowptr[i + 1];
    __syncthreads();
    if (t >= 76) return;
    float4* aggv = (float4*)g_agg;
    if (t == 75) { aggv[(size_t)i * 76 + 75] = make_float4(0.f, 0.f, 0.f, 0.f); return; }
    const float4* h2v = (const float4*)g_h2;
    const float4* e1v = (const float4*)(g_e1p + l * 6 * KA);
    const float4* e2v = (const float4*)(g_e2p + l * 3 * KA);
    float4 sc = ((const float4*)g_scale)[t];
    float4 sh = ((const float4*)g_shift)[t];
    float4 acc;
    {   // self loop: h[i]
        float4 xx = h2v[(size_t)i * 76 + t];
        acc.x = fmaf(xx.x, sc.x, sh.x);
        acc.y = fmaf(xx.y, sc.y, sh.y);
        acc.z = fmaf(xx.z, sc.z, sh.z);
        acc.w = fmaf(xx.w, sc.w, sh.w);
        if (relu) {
            acc.x = fmaxf(acc.x, 0.f); acc.y = fmaxf(acc.y, 0.f);
            acc.z = fmaxf(acc.z, 0.f); acc.w = fmaxf(acc.w, 0.f);
        }
    }
    #pragma unroll
    for (int tt = 0; tt < 6; tt++) {
        float ct = (float)(scnt[tt] + (tt == 0 ? 1 : 0));   // +1: self-loop edge_attr = (0,0)
        if (ct != 0.f) {
            float4 e = e1v[tt * 76 + t];
            acc.x = fmaf(ct, e.x, acc.x); acc.y = fmaf(ct, e.y, acc.y);
            acc.z = fmaf(ct, e.z, acc.z); acc.w = fmaf(ct, e.w, acc.w);
        }
    }
    #pragma unroll
    for (int dd = 0; dd < 3; dd++) {
        float cd = (float)(scnt[6 + dd] + (dd == 0 ? 1 : 0));
        if (cd != 0.f) {
            float4 e = e2v[dd * 76 + t];
            acc.x = fmaf(cd, e.x, acc.x); acc.y = fmaf(cd, e.y, acc.y);
            acc.z = fmaf(cd, e.z, acc.z); acc.w = fmaf(cd, e.w, acc.w);
        }
    }
    for (int p = srange[0]; p < srange[1]; p++) {
        int j = g_srclist[p];
        float4 xx = h2v[(size_t)j * 76 + t];
        float4 a;
        a.x = fmaf(xx.x, sc.x, sh.x);
        a.y = fmaf(xx.y, sc.y, sh.y);
        a.z = fmaf(xx.z, sc.z, sh.z);
        a.w = fmaf(xx.w, sc.w, sh.w);
        if (relu) {
            a.x = fmaxf(a.x, 0.f); a.y = fmaxf(a.y, 0.f);
            a.z = fmaxf(a.z, 0.f); a.w = fmaxf(a.w, 0.f);
        }
        acc.x += a.x; acc.y += a.y; acc.z += a.z; acc.w += a.w;
    }
    aggv[(size_t)i * 76 + t] = acc;
}

// Fused-precision GEMM: C = act(A @ B + bias) via 3xTF32 split (fp32-class accuracy).
// which==0: T = relu(agg @ W1p + b1p)    (K=304, N=640, ldc/store limit 608)
// which==1: h2 = T @ W2p + b2p           (K=608, N=320, ldc/store limit 304)
__global__ void k_gemm(int which, int l) {
    const float *A, *B, *bias;
    float* C;
    int K, NBW, ldc, relu;
    if (which == 0) {
        A = g_agg; B = g_W1p + (size_t)l * KA * NB1; bias = g_b1p + l * NB1;
        C = g_T; K = KA; NBW = NB1; ldc = NT; relu = 1;
    } else {
        A = g_T; B = g_W2p + (size_t)l * NT * NB2; bias = g_b2p + l * NB2;
        C = g_h2; K = NT; NBW = NB2; ldc = KA; relu = 0;
    }
    const int M = NNODE;
    __shared__ float As[128][16];
    __shared__ float Bs[16][68];
    __shared__ float Cs[128][68];
    int tid = threadIdx.x;          // 256
    int wid = tid >> 5;
    int wm = wid & 3;               // 4 warps along M
    int wn = wid >> 2;              // 2 warps along N
    int bm0 = blockIdx.x * 128;
    int bn0 = blockIdx.y * 64;

    wmma::fragment<wmma::accumulator, 16, 16, 8, float> acc[2][2];
    #pragma unroll
    for (int im = 0; im < 2; im++)
        #pragma unroll
        for (int in_ = 0; in_ < 2; in_++)
            wmma::fill_fragment(acc[im][in_], 0.f);

    for (int k0 = 0; k0 < K; k0 += 16) {
        #pragma unroll
        for (int it = 0; it < 2; it++) {
            int idx = tid + it * 256;       // 0..511
            int r = idx >> 2, c4 = idx & 3;
            float4 v = make_float4(0.f, 0.f, 0.f, 0.f);
            int gr = bm0 + r;
            if (gr < M) v = *(const float4*)(A + (size_t)gr * K + k0 + c4 * 4);
            *(float4*)(&As[r][c4 * 4]) = v;
        }
        {
            int r = tid >> 4, c4 = tid & 15;
            float4 v = *(const float4*)(B + (size_t)(k0 + r) * NBW + bn0 + c4 * 4);
            *(float4*)(&Bs[r][c4 * 4]) = v;
        }
        __syncthreads();
        #pragma unroll
        for (int kk = 0; kk < 2; kk++) {
            wmma::fragment<wmma::matrix_a, 16, 16, 8, wmma::precision::tf32, wmma::row_major> ah[2], al[2];
            wmma::fragment<wmma::matrix_b, 16, 16, 8, wmma::precision::tf32, wmma::row_major> bh[2], bl[2];
            #pragma unroll
            for (int im = 0; im < 2; im++) {
                wmma::load_matrix_sync(ah[im], &As[wm * 32 + im * 16][kk * 8], 16);
                #pragma unroll
                for (int e = 0; e < ah[im].num_elements; e++) {
                    float xv = ah[im].x[e];
                    float hi = wmma::__float_to_tf32(xv);
                    ah[im].x[e] = hi;
                    al[im].x[e] = wmma::__float_to_tf32(xv - hi);
                }
            }
            #pragma unroll
            for (int in_ = 0; in_ < 2; in_++) {
                wmma::load_matrix_sync(bh[in_], &Bs[kk * 8][wn * 32 + in_ * 16], 68);
                #pragma unroll
                for (int e = 0; e < bh[in_].num_elements; e++) {
                    float xv = bh[in_].x[e];
                    float hi = wmma::__float_to_tf32(xv);
                    bh[in_].x[e] = hi;
                    bl[in_].x[e] = wmma::__float_to_tf32(xv - hi);
                }
            }
            #pragma unroll
            for (int im = 0; im < 2; im++)
                #pragma unroll
                for (int in_ = 0; in_ < 2; in_++) {
                    wmma::mma_sync(acc[im][in_], ah[im], bh[in_], acc[im][in_]);
                    wmma::mma_sync(acc[im][in_], al[im], bh[in_], acc[im][in_]);
                    wmma::mma_sync(acc[im][in_], ah[im], bl[in_], acc[im][in_]);
                }
        }
        __syncthreads();
    }
    #pragma unroll
    for (int im = 0; im < 2; im++)
        #pragma unroll
        for (int in_ = 0; in_ < 2; in_++)
            wmma::store_matrix_sync(&Cs[wm * 32 + im * 16][wn * 32 + in_ * 16],
                                    acc[im][in_], 68, wmma::mem_row_major);
    __syncthreads();
    #pragma unroll 4
    for (int rr = tid >> 6; rr < 128; rr += 4) {
        int c = tid & 63;
        int gr = bm0 + rr, gc = bn0 + c;
        if (gr < M && gc < ldc) {
            float v = Cs[rr][c] + bias[gc];
            if (relu) v = fmaxf(v, 0.f);
            C[(size_t)gr * ldc + gc] = v;
        }
    }
}

__global__ void k_zero_stats() {
    int c = threadIdx.x;
    if (c < 2 * KA) g_stats[c] = 0.f;
}

__global__ void k_stats() {
    int c = threadIdx.x;            // 320, active < 300
    if (c >= 300) return;
    int r0 = blockIdx.x * 250;
    int r1 = r0 + 250; if (r1 > NNODE) r1 = NNODE;
    float s = 0.f, s2 = 0.f;
    for (int r = r0; r < r1; r++) {
        float v = g_h2[(size_t)r * KA + c];
        s += v;
        s2 = fmaf(v, v, s2);
    }
    atomicAdd(&g_stats[c], s);
    atomicAdd(&g_stats[KA + c], s2);
}

__global__ void k_bn(const float* __restrict__ gamma, const float* __restrict__ beta, int l) {
    int c = threadIdx.x;            // 320
    if (c >= KA) return;
    if (c < 300) {
        float mu = g_stats[c] * (1.f / NNODE);
        float var = g_stats[KA + c] * (1.f / NNODE) - mu * mu;
        float rstd = rsqrtf(var + 1e-5f);
        float sc = rstd * gamma[l * 300 + c];
        g_scale[c] = sc;
        g_shift[c] = beta[l * 300 + c] - mu * sc;
    } else {
        g_scale[c] = 0.f;
        g_shift[c] = 0.f;
    }
}

__global__ void k_pool(float* __restrict__ out) {
    int g = blockIdx.x;
    int t = threadIdx.x;            // 96, active < 75 (300/4 chunks)
    if (t >= 75) return;
    int i0 = g_gstart[g], i1 = g_gstart[g + 1];
    const float4* h2v = (const float4*)g_h2;
    float4 sc = ((const float4*)g_scale)[t];
    float4 sh = ((const float4*)g_shift)[t];
    float4 acc = make_float4(0.f, 0.f, 0.f, 0.f);
    for (int i = i0; i < i1; i++) {
        float4 xx = h2v[(size_t)i * 76 + t];
        acc.x += fmaf(xx.x, sc.x, sh.x);
        acc.y += fmaf(xx.y, sc.y, sh.y);
        acc.z += fmaf(xx.z, sc.z, sh.z);
        acc.w += fmaf(xx.w, sc.w, sh.w);
    }
    float inv = g_ginv[g];
    acc.x *= inv; acc.y *= inv; acc.z *= inv; acc.w *= inv;
    ((float4*)out)[(size_t)g * 75 + t] = acc;
}

// ---------------- host launcher ----------------
extern "C" void kernel_launch(void* const* d_in, const int* in_sizes, int n_in,
                              void* d_out, int out_size) {
    const int* x          = (const int*)d_in[0];
    const int* edge_index = (const int*)d_in[1];
    const int* edge_attr  = (const int*)d_in[2];
    const int* batch      = (const int*)d_in[3];
    const float* x_emb1   = (const float*)d_in[4];
    const float* x_emb2   = (const float*)d_in[5];
    const float* e1       = (const float*)d_in[6];
    const float* e2       = (const float*)d_in[7];
    const float* W1       = (const float*)d_in[8];
    const float* b1       = (const float*)d_in[9];
    const float* W2       = (const float*)d_in[10];
    const float* b2       = (const float*)d_in[11];
    const float* gamma    = (const float*)d_in[12];
    const float* beta     = (const float*)d_in[13];
    float* out = (float*)d_out;

    k_zero<<<(NNODE * 9 + 255) / 256, 256>>>();
    k_prep_w1<<<(NLAYER * KA * NB1 + 255) / 256, 256>>>(W1, b1);
    k_prep_w2<<<(NLAYER * NT * NB2 + 255) / 256, 256>>>(W2, b2);
    k_prep_small<<<(NLAYER * 6 * KA + 255) / 256, 256>>>(e1, e2);
    k_count<<<(NEDGE + 255) / 256, 256>>>(edge_index, edge_attr);
    k_scan<<<1, 1024>>>();
    k_fill<<<(NEDGE + 255) / 256, 256>>>(edge_index);
    k_h0<<<(int)(((size_t)NNODE * KA + 255) / 256), 256>>>(x, x_emb1, x_emb2);
    k_gstart<<<(NNODE + 255) / 256, 256>>>(batch);
    k_ginv<<<(NGRAPH + 255) / 256, 256>>>();

    for (int l = 0; l < NLAYER; l++) {
        k_agg<<<NNODE, 96>>>(l, (l > 0) ? 1 : 0);
        dim3 g1((NNODE + 127) / 128, NB1 / 64);
        k_gemm<<<g1, 256>>>(0, l);
        dim3 g2((NNODE + 127) / 128, NB2 / 64);
        k_gemm<<<g2, 256>>>(1, l);
        k_zero_stats<<<1, 2 * KA>>>();
        k_stats<<<400, 320>>>();
        k_bn<<<1, 320>>>(gamma, beta, l);
    }
    k_pool<<<NGRAPH, 96>>>(out);
}

// round 4
// speedup vs baseline: 2.7535x; 2.7535x over previous
#include <cuda_runtime.h>
#include <cuda_bf16.h>
#include <cstdint>

#define NNODE 100000
#define NEDGE 200000
#define NGRAPH 5000
#define NLAYER 5
#define KA 304      // h2 fp32 stride (300 padded to 304)
#define KAB 320     // agg bf16 K stride
#define NTB 640     // T bf16 K stride / GEMM1 N
#define NB1 640
#define NB2 320

// ---------------- device scratch ----------------
__device__ float g_h2[(size_t)NNODE * KA];               // pre-norm layer output (fp32)
__device__ __nv_bfloat16 g_aggh[(size_t)NNODE * KAB];    // agg split hi
__device__ __nv_bfloat16 g_aggl[(size_t)NNODE * KAB];    // agg split lo
__device__ __nv_bfloat16 g_Th[(size_t)NNODE * NTB];      // hidden split hi
__device__ __nv_bfloat16 g_Tl[(size_t)NNODE * NTB];      // hidden split lo
__device__ __nv_bfloat16 g_B1h[NLAYER * 640 * 320];      // W1^T split  [l][n][k]
__device__ __nv_bfloat16 g_B1l[NLAYER * 640 * 320];
__device__ __nv_bfloat16 g_B2h[NLAYER * 320 * 640];      // W2^T split  [l][n][k]
__device__ __nv_bfloat16 g_B2l[NLAYER * 320 * 640];
__device__ float g_b1p[NLAYER * NB1];
__device__ float g_b2p[NLAYER * NB2];
__device__ float g_e1p[NLAYER * 6 * KA];
__device__ float g_e2p[NLAYER * 3 * KA];
__device__ float g_scale[KA];
__device__ float g_shift[KA];
__device__ float g_stats[2 * KA];
__device__ int   g_deg[NNODE];
__device__ int   g_cursor[NNODE];
__device__ int   g_rowptr[NNODE + 1];
__device__ int   g_srclist[NEDGE];
__device__ int   g_ecnt[(size_t)NNODE * 9];
__device__ int   g_gstart[NGRAPH + 1];
__device__ float g_ginv[NGRAPH];

// ---------------- helpers ----------------
__device__ __forceinline__ uint32_t smem_u32(const void* p) {
    uint32_t a;
    asm("{ .reg .u64 t; cvta.to.shared.u64 t, %1; cvt.u32.u64 %0, t; }" : "=r"(a) : "l"(p));
    return a;
}
__device__ __forceinline__ void cp16(uint32_t dst, const void* src, int srcsize) {
    asm volatile("cp.async.cg.shared.global [%0], [%1], 16, %2;"
                 :: "r"(dst), "l"(src), "r"(srcsize) : "memory");
}
#define CP_COMMIT() asm volatile("cp.async.commit_group;" ::: "memory")
#define CP_WAIT1()  asm volatile("cp.async.wait_group 1;" ::: "memory")
#define CP_WAIT0()  asm volatile("cp.async.wait_group 0;" ::: "memory")

__device__ __forceinline__ void ldsm_x4(uint32_t* r, uint32_t addr) {
    asm volatile("ldmatrix.sync.aligned.m8n8.x4.shared.b16 {%0,%1,%2,%3}, [%4];"
                 : "=r"(r[0]), "=r"(r[1]), "=r"(r[2]), "=r"(r[3]) : "r"(addr));
}
__device__ __forceinline__ void ldsm_x2(uint32_t* r, uint32_t addr) {
    asm volatile("ldmatrix.sync.aligned.m8n8.x2.shared.b16 {%0,%1}, [%2];"
                 : "=r"(r[0]), "=r"(r[1]) : "r"(addr));
}
__device__ __forceinline__ void mma_bf16(float* d, const uint32_t* a, const uint32_t* b) {
    asm volatile("mma.sync.aligned.m16n8k16.row.col.f32.bf16.bf16.f32 "
                 "{%0,%1,%2,%3}, {%4,%5,%6,%7}, {%8,%9}, {%0,%1,%2,%3};"
                 : "+f"(d[0]), "+f"(d[1]), "+f"(d[2]), "+f"(d[3])
                 : "r"(a[0]), "r"(a[1]), "r"(a[2]), "r"(a[3]), "r"(b[0]), "r"(b[1]));
}

// ---------------- setup kernels ----------------
__global__ void k_zero() {
    int idx = blockIdx.x * blockDim.x + threadIdx.x;
    if (idx < NNODE) { g_deg[idx] = 0; g_cursor[idx] = 0; }
    if (idx < NNODE * 9) g_ecnt[idx] = 0;
}

__global__ void k_prep_b1(const float* __restrict__ W1, const float* __restrict__ b1) {
    int idx = blockIdx.x * blockDim.x + threadIdx.x;
    if (idx < NLAYER * 640 * 320) {
        int k = idx % 320;
        int n = (idx / 320) % 640;
        int l = idx / (320 * 640);
        float w = (k < 300 && n < 600) ? W1[((size_t)l * 300 + k) * 600 + n] : 0.f;
        __nv_bfloat16 h = __float2bfloat16(w);
        g_B1h[idx] = h;
        g_B1l[idx] = __float2bfloat16(w - __bfloat162float(h));
    }
    if (idx < NLAYER * NB1) {
        int n = idx % NB1, l = idx / NB1;
        g_b1p[idx] = (n < 600) ? b1[l * 600 + n] : 0.f;
    }
}

__global__ void k_prep_b2(const float* __restrict__ W2, const float* __restrict__ b2) {
    int idx = blockIdx.x * blockDim.x + threadIdx.x;
    if (idx < NLAYER * 320 * 640) {
        int k = idx % 640;
        int n = (idx / 640) % 320;
        int l = idx / (640 * 320);
        float w = (k < 600 && n < 300) ? W2[((size_t)l * 600 + k) * 300 + n] : 0.f;
        __nv_bfloat16 h = __float2bfloat16(w);
        g_B2h[idx] = h;
        g_B2l[idx] = __float2bfloat16(w - __bfloat162float(h));
    }
    if (idx < NLAYER * NB2) {
        int n = idx % NB2, l = idx / NB2;
        g_b2p[idx] = (n < 300) ? b2[l * 300 + n] : 0.f;
    }
}

__global__ void k_prep_small(const float* __restrict__ e1, const float* __restrict__ e2) {
    int idx = blockIdx.x * blockDim.x + threadIdx.x;
    if (idx < NLAYER * 6 * KA) {
        int c = idx % KA, r = idx / KA;
        g_e1p[idx] = (c < 300) ? e1[(size_t)r * 300 + c] : 0.f;
    }
    if (idx < NLAYER * 3 * KA) {
        int c = idx % KA, r = idx / KA;
        g_e2p[idx] = (c < 300) ? e2[(size_t)r * 300 + c] : 0.f;
    }
    if (idx < KA) { g_scale[idx] = 1.f; g_shift[idx] = 0.f; }
}

__global__ void k_count(const int* __restrict__ edge_index, const int* __restrict__ edge_attr) {
    int e = blockIdx.x * blockDim.x + threadIdx.x;
    if (e >= NEDGE) return;
    int dst = edge_index[NEDGE + e];
    int a0 = edge_attr[2 * e];
    int a1 = edge_attr[2 * e + 1];
    atomicAdd(&g_deg[dst], 1);
    atomicAdd(&g_ecnt[(size_t)dst * 9 + a0], 1);
    atomicAdd(&g_ecnt[(size_t)dst * 9 + 6 + a1], 1);
}

__global__ void k_scan() {
    __shared__ int wsum[32];
    __shared__ int carry;
    int t = threadIdx.x;
    int lane = t & 31, w = t >> 5;
    if (t == 0) carry = 0;
    __syncthreads();
    for (int base = 0; base < NNODE; base += 1024) {
        int v = (base + t < NNODE) ? g_deg[base + t] : 0;
        int s = v;
        #pragma unroll
        for (int o = 1; o < 32; o <<= 1) {
            int u = __shfl_up_sync(0xffffffffu, s, o);
            if (lane >= o) s += u;
        }
        if (lane == 31) wsum[w] = s;
        __syncthreads();
        if (w == 0) {
            int ws = wsum[lane];
            #pragma unroll
            for (int o = 1; o < 32; o <<= 1) {
                int u = __shfl_up_sync(0xffffffffu, ws, o);
                if (lane >= o) ws += u;
            }
            wsum[lane] = ws;
        }
        __syncthreads();
        int excl = s - v + (w > 0 ? wsum[w - 1] : 0) + carry;
        if (base + t < NNODE) g_rowptr[base + t] = excl;
        int total = wsum[31];
        __syncthreads();
        if (t == 0) carry += total;
        __syncthreads();
    }
    if (t == 0) g_rowptr[NNODE] = carry;
}

__global__ void k_fill(const int* __restrict__ edge_index) {
    int e = blockIdx.x * blockDim.x + threadIdx.x;
    if (e >= NEDGE) return;
    int dst = edge_index[NEDGE + e];
    int src = edge_index[e];
    int pos = g_rowptr[dst] + atomicAdd(&g_cursor[dst], 1);
    g_srclist[pos] = src;
}

__global__ void k_h0(const int* __restrict__ x,
                     const float* __restrict__ emb1, const float* __restrict__ emb2) {
    size_t idx = (size_t)blockIdx.x * blockDim.x + threadIdx.x;
    if (idx >= (size_t)NNODE * KA) return;
    int c = (int)(idx % KA);
    int i = (int)(idx / KA);
    if (c < 300) {
        int a0 = x[2 * i], a1 = x[2 * i + 1];
        g_h2[idx] = emb1[(size_t)a0 * 300 + c] + emb2[(size_t)a1 * 300 + c];
    } else {
        g_h2[idx] = 0.f;
    }
}

__global__ void k_gstart(const int* __restrict__ batch) {
    int i = blockIdx.x * blockDim.x + threadIdx.x;
    if (i >= NNODE) return;
    int b = batch[i];
    int bp = (i == 0) ? -1 : batch[i - 1];
    for (int g = bp + 1; g <= b; g++) g_gstart[g] = i;
    if (i == NNODE - 1) {
        for (int g = b + 1; g <= NGRAPH; g++) g_gstart[g] = NNODE;
    }
}

__global__ void k_ginv() {
    int g = blockIdx.x * blockDim.x + threadIdx.x;
    if (g >= NGRAPH) return;
    int c = g_gstart[g + 1] - g_gstart[g];
    g_ginv[g] = (c > 0) ? (1.f / (float)c) : 0.f;
}

// ---------------- aggregation (BN-affine fused; writes bf16 hi/lo) ----------------
__global__ void k_agg(int l, int relu) {
    int i = blockIdx.x;
    int t = threadIdx.x;     // 96 threads
    __shared__ int scnt[9];
    __shared__ int srange[2];
    if (t < 9) scnt[t] = g_ecnt[(size_t)i * 9 + t];
    else if (t == 9) srange[0] = g_rowptr[i];
    else if (t == 10) srange[1] = g_rowptr[i + 1];
    __syncthreads();
    if (t >= 80) return;
    __nv_bfloat162* oh = (__nv_bfloat162*)(g_aggh + (size_t)i * KAB);
    __nv_bfloat162* ol = (__nv_bfloat162*)(g_aggl + (size_t)i * KAB);
    if (t >= 75) {  // cols 300..319: zero pad
        __nv_bfloat162 z; z.x = __float2bfloat16(0.f); z.y = z.x;
        oh[2 * t] = z; oh[2 * t + 1] = z;
        ol[2 * t] = z; ol[2 * t + 1] = z;
        return;
    }
    const float4* h2v = (const float4*)g_h2;
    const float4* e1v = (const float4*)(g_e1p + l * 6 * KA);
    const float4* e2v = (const float4*)(g_e2p + l * 3 * KA);
    float4 sc = ((const float4*)g_scale)[t];
    float4 sh = ((const float4*)g_shift)[t];
    float4 acc;
    {   // self loop
        float4 xx = h2v[(size_t)i * 76 + t];
        acc.x = fmaf(xx.x, sc.x, sh.x);
        acc.y = fmaf(xx.y, sc.y, sh.y);
        acc.z = fmaf(xx.z, sc.z, sh.z);
        acc.w = fmaf(xx.w, sc.w, sh.w);
        if (relu) {
            acc.x = fmaxf(acc.x, 0.f); acc.y = fmaxf(acc.y, 0.f);
            acc.z = fmaxf(acc.z, 0.f); acc.w = fmaxf(acc.w, 0.f);
        }
    }
    #pragma unroll
    for (int tt = 0; tt < 6; tt++) {
        float ct = (float)(scnt[tt] + (tt == 0 ? 1 : 0));
        if (ct != 0.f) {
            float4 e = e1v[tt * 76 + t];
            acc.x = fmaf(ct, e.x, acc.x); acc.y = fmaf(ct, e.y, acc.y);
            acc.z = fmaf(ct, e.z, acc.z); acc.w = fmaf(ct, e.w, acc.w);
        }
    }
    #pragma unroll
    for (int dd = 0; dd < 3; dd++) {
        float cd = (float)(scnt[6 + dd] + (dd == 0 ? 1 : 0));
        if (cd != 0.f) {
            float4 e = e2v[dd * 76 + t];
            acc.x = fmaf(cd, e.x, acc.x); acc.y = fmaf(cd, e.y, acc.y);
            acc.z = fmaf(cd, e.z, acc.z); acc.w = fmaf(cd, e.w, acc.w);
        }
    }
    for (int p = srange[0]; p < srange[1]; p++) {
        int j = g_srclist[p];
        float4 xx = h2v[(size_t)j * 76 + t];
        float4 a;
        a.x = fmaf(xx.x, sc.x, sh.x);
        a.y = fmaf(xx.y, sc.y, sh.y);
        a.z = fmaf(xx.z, sc.z, sh.z);
        a.w = fmaf(xx.w, sc.w, sh.w);
        if (relu) {
            a.x = fmaxf(a.x, 0.f); a.y = fmaxf(a.y, 0.f);
            a.z = fmaxf(a.z, 0.f); a.w = fmaxf(a.w, 0.f);
        }
        acc.x += a.x; acc.y += a.y; acc.z += a.z; acc.w += a.w;
    }
    __nv_bfloat162 h01, h23, l01, l23;
    h01.x = __float2bfloat16(acc.x); l01.x = __float2bfloat16(acc.x - __bfloat162float(h01.x));
    h01.y = __float2bfloat16(acc.y); l01.y = __float2bfloat16(acc.y - __bfloat162float(h01.y));
    h23.x = __float2bfloat16(acc.z); l23.x = __float2bfloat16(acc.z - __bfloat162float(h23.x));
    h23.y = __float2bfloat16(acc.w); l23.y = __float2bfloat16(acc.w - __bfloat162float(h23.y));
    oh[2 * t] = h01; oh[2 * t + 1] = h23;
    ol[2 * t] = l01; ol[2 * t + 1] = l23;
}

// ---------------- mma.sync bf16-split GEMM ----------------
// Block 128x160, 8 warps (2M x 4N), warp tile 64x40, K-chunk 32, cp.async double buffer.
// D = Ah@Bh + Al@Bh + Ah@Bl (fp32 acc).
// which==0: T = relu(agg @ W1 + b1) -> bf16 hi/lo   (K=320, 10 chunks)
// which==1: h2 = T @ W2 + b2        -> fp32         (K=640, 20 chunks)
#define ROWB 80
#define OFF_AH 0
#define OFF_AL 10240
#define OFF_BH 20480
#define OFF_BL 33280
#define BUF_B  46080
#define SM_TOTAL (2 * BUF_B)

__global__ void __launch_bounds__(256, 1)
k_gemm(int which, int l) {
    extern __shared__ char smem[];
    uint32_t sbase = smem_u32(smem);
    int tid = threadIdx.x;
    int wid = tid >> 5;
    int lane = tid & 31;
    int m0 = blockIdx.y * 128;
    int n0 = blockIdx.x * 160;
    int wm0 = (wid & 1) * 64;
    int wn0 = (wid >> 1) * 40;

    const __nv_bfloat16 *Ah, *Al, *Bh, *Bl;
    const float* bias;
    int lda, ldb, nchunk;
    if (which == 0) {
        Ah = g_aggh; Al = g_aggl; lda = KAB;
        Bh = g_B1h + (size_t)l * 640 * 320; Bl = g_B1l + (size_t)l * 640 * 320; ldb = 320;
        bias = g_b1p + l * NB1; nchunk = 10;
    } else {
        Ah = g_Th; Al = g_Tl; lda = NTB;
        Bh = g_B2h + (size_t)l * 320 * 640; Bl = g_B2l + (size_t)l * 320 * 640; ldb = 640;
        bias = g_b2p + l * NB2; nchunk = 20;
    }

    float acc[4][5][4];
    #pragma unroll
    for (int a = 0; a < 4; a++)
        #pragma unroll
        for (int b = 0; b < 5; b++)
            #pragma unroll
            for (int c = 0; c < 4; c++) acc[a][b][c] = 0.f;

    auto load_chunk = [&](int c, int buf) {
        int k0 = c * 32;
        uint32_t bb = sbase + buf * BUF_B;
        // A hi/lo: 128 rows x 32 bf16 (4x16B per row) x2 mats = 1024 ops
        #pragma unroll
        for (int it = 0; it < 4; it++) {
            int idx = tid + it * 256;
            int mat = idx >> 9;
            int rem = idx & 511;
            int r = rem >> 2, cc = rem & 3;
            int gr = m0 + r;
            const __nv_bfloat16* src = (mat ? Al : Ah) + (size_t)gr * lda + k0 + cc * 8;
            cp16(bb + (mat ? OFF_AL : OFF_AH) + r * ROWB + cc * 16, src, gr < NNODE ? 16 : 0);
        }
        // B hi/lo: 160 rows x 32 bf16 x2 = 1280 ops
        #pragma unroll
        for (int it = 0; it < 5; it++) {
            int idx = tid + it * 256;
            int mat = idx >= 640;
            int rem = mat ? idx - 640 : idx;
            int r = rem >> 2, cc = rem & 3;
            const __nv_bfloat16* src = (mat ? Bl : Bh) + (size_t)(n0 + r) * ldb + k0 + cc * 8;
            cp16(bb + (mat ? OFF_BL : OFF_BH) + r * ROWB + cc * 16, src, 16);
        }
    };

    load_chunk(0, 0);
    CP_COMMIT();

    int l8 = lane & 7;
    int ars = (lane >> 3) & 1;     // A row +8
    int aks = lane >> 4;           // A k +8
    int bl8 = lane & 7;            // B uses lanes 0-15; safe addresses for all
    int bks = (lane >> 3) & 1;

    for (int c = 0; c < nchunk; c++) {
        int buf = c & 1;
        if (c + 1 < nchunk) {
            load_chunk(c + 1, buf ^ 1);
            CP_COMMIT();
            CP_WAIT1();
        } else {
            CP_WAIT0();
        }
        __syncthreads();
        uint32_t bb = sbase + buf * BUF_B;
        #pragma unroll
        for (int ks = 0; ks < 2; ks++) {
            uint32_t a_h[4][4], a_l[4][4], b_h[5][2], b_l[5][2];
            uint32_t a_addr = bb + (uint32_t)((wm0 + l8 + ars * 8) * ROWB + (ks * 16 + aks * 8) * 2);
            #pragma unroll
            for (int tm = 0; tm < 4; tm++) {
                ldsm_x4(a_h[tm], a_addr + OFF_AH + tm * 16 * ROWB);
                ldsm_x4(a_l[tm], a_addr + OFF_AL + tm * 16 * ROWB);
            }
            uint32_t b_addr = bb + (uint32_t)((wn0 + bl8) * ROWB + (ks * 16 + bks * 8) * 2);
            #pragma unroll
            for (int tn = 0; tn < 5; tn++) {
                ldsm_x2(b_h[tn], b_addr + OFF_BH + tn * 8 * ROWB);
                ldsm_x2(b_l[tn], b_addr + OFF_BL + tn * 8 * ROWB);
            }
            #pragma unroll
            for (int tm = 0; tm < 4; tm++)
                #pragma unroll
                for (int tn = 0; tn < 5; tn++) {
                    mma_bf16(acc[tm][tn], a_h[tm], b_h[tn]);
                    mma_bf16(acc[tm][tn], a_l[tm], b_h[tn]);
                    mma_bf16(acc[tm][tn], a_h[tm], b_l[tn]);
                }
        }
        __syncthreads();
    }

    // epilogue
    int gl = lane >> 2;
    int gc = (lane & 3) * 2;
    #pragma unroll
    for (int tm = 0; tm < 4; tm++) {
        #pragma unroll
        for (int half = 0; half < 2; half++) {
            int row = m0 + wm0 + tm * 16 + gl + half * 8;
            if (row >= NNODE) continue;
            #pragma unroll
            for (int tn = 0; tn < 5; tn++) {
                int col = n0 + wn0 + tn * 8 + gc;
                float v0 = acc[tm][tn][half * 2 + 0] + bias[col];
                float v1 = acc[tm][tn][half * 2 + 1] + bias[col + 1];
                if (which == 0) {
                    v0 = fmaxf(v0, 0.f);
                    v1 = fmaxf(v1, 0.f);
                    __nv_bfloat162 hv, lv;
                    hv.x = __float2bfloat16(v0); lv.x = __float2bfloat16(v0 - __bfloat162float(hv.x));
                    hv.y = __float2bfloat16(v1); lv.y = __float2bfloat16(v1 - __bfloat162float(hv.y));
                    size_t off = ((size_t)row * NTB + col) >> 1;
                    ((__nv_bfloat162*)g_Th)[off] = hv;
                    ((__nv_bfloat162*)g_Tl)[off] = lv;
                } else {
                    if (col < KA) {
                        float2 v; v.x = v0; v.y = v1;
                        *(float2*)(g_h2 + (size_t)row * KA + col) = v;
                    }
                }
            }
        }
    }
}

__global__ void k_zero_stats() {
    int c = threadIdx.x;
    if (c < 2 * KA) g_stats[c] = 0.f;
}

__global__ void k_stats() {
    int c = threadIdx.x;
    if (c >= 300) return;
    int r0 = blockIdx.x * 250;
    int r1 = r0 + 250; if (r1 > NNODE) r1 = NNODE;
    float s = 0.f, s2 = 0.f;
    for (int r = r0; r < r1; r++) {
        float v = g_h2[(size_t)r * KA + c];
        s += v;
        s2 = fmaf(v, v, s2);
    }
    atomicAdd(&g_stats[c], s);
    atomicAdd(&g_stats[KA + c], s2);
}

__global__ void k_bn(const float* __restrict__ gamma, const float* __restrict__ beta, int l) {
    int c = threadIdx.x;
    if (c >= KA) return;
    if (c < 300) {
        float mu = g_stats[c] * (1.f / NNODE);
        float var = g_stats[KA + c] * (1.f / NNODE) - mu * mu;
        float rstd = rsqrtf(var + 1e-5f);
        float sc = rstd * gamma[l * 300 + c];
        g_scale[c] = sc;
        g_shift[c] = beta[l * 300 + c] - mu * sc;
    } else {
        g_scale[c] = 0.f;
        g_shift[c] = 0.f;
    }
}

__global__ void k_pool(float* __restrict__ out) {
    int g = blockIdx.x;
    int t = threadIdx.x;
    if (t >= 75) return;
    int i0 = g_gstart[g], i1 = g_gstart[g + 1];
    const float4* h2v = (const float4*)g_h2;
    float4 sc = ((const float4*)g_scale)[t];
    float4 sh = ((const float4*)g_shift)[t];
    float4 acc = make_float4(0.f, 0.f, 0.f, 0.f);
    for (int i = i0; i < i1; i++) {
        float4 xx = h2v[(size_t)i * 76 + t];
        acc.x += fmaf(xx.x, sc.x, sh.x);
        acc.y += fmaf(xx.y, sc.y, sh.y);
        acc.z += fmaf(xx.z, sc.z, sh.z);
        acc.w += fmaf(xx.w, sc.w, sh.w);
    }
    float inv = g_ginv[g];
    acc.x *= inv; acc.y *= inv; acc.z *= inv; acc.w *= inv;
    ((float4*)out)[(size_t)g * 75 + t] = acc;
}

// ---------------- host launcher ----------------
extern "C" void kernel_launch(void* const* d_in, const int* in_sizes, int n_in,
                              void* d_out, int out_size) {
    const int* x          = (const int*)d_in[0];
    const int* edge_index = (const int*)d_in[1];
    const int* edge_attr  = (const int*)d_in[2];
    const int* batch      = (const int*)d_in[3];
    const float* x_emb1   = (const float*)d_in[4];
    const float* x_emb2   = (const float*)d_in[5];
    const float* e1       = (const float*)d_in[6];
    const float* e2       = (const float*)d_in[7];
    const float* W1       = (const float*)d_in[8];
    const float* b1       = (const float*)d_in[9];
    const float* W2       = (const float*)d_in[10];
    const float* b2       = (const float*)d_in[11];
    const float* gamma    = (const float*)d_in[12];
    const float* beta     = (const float*)d_in[13];
    float* out = (float*)d_out;

    static int smem_set = 0;
    if (!smem_set) {
        cudaFuncSetAttribute(k_gemm, cudaFuncAttributeMaxDynamicSharedMemorySize, SM_TOTAL);
        smem_set = 1;
    }

    k_zero<<<(NNODE * 9 + 255) / 256, 256>>>();
    k_prep_b1<<<(NLAYER * 640 * 320 + 255) / 256, 256>>>(W1, b1);
    k_prep_b2<<<(NLAYER * 320 * 640 + 255) / 256, 256>>>(W2, b2);
    k_prep_small<<<(NLAYER * 6 * KA + 255) / 256, 256>>>(e1, e2);
    k_count<<<(NEDGE + 255) / 256, 256>>>(edge_index, edge_attr);
    k_scan<<<1, 1024>>>();
    k_fill<<<(NEDGE + 255) / 256, 256>>>(edge_index);
    k_h0<<<(int)(((size_t)NNODE * KA + 255) / 256), 256>>>(x, x_emb1, x_emb2);
    k_gstart<<<(NNODE + 255) / 256, 256>>>(batch);
    k_ginv<<<(NGRAPH + 255) / 256, 256>>>();

    for (int l = 0; l < NLAYER; l++) {
        k_agg<<<NNODE, 96>>>(l, (l > 0) ? 1 : 0);
        dim3 g1(4, (NNODE + 127) / 128);
        k_gemm<<<g1, 256, SM_TOTAL>>>(0, l);
        dim3 g2(2, (NNODE + 127) / 128);
        k_gemm<<<g2, 256, SM_TOTAL>>>(1, l);
        k_zero_stats<<<1, 2 * KA>>>();
        k_stats<<<400, 320>>>();
        k_bn<<<1, 320>>>(gamma, beta, l);
    }
    k_pool<<<NGRAPH, 96>>>(out);
}